// round 14
// baseline (speedup 1.0000x reference)
#include <cuda_runtime.h>
#include <cuda_fp16.h>
#include <stdint.h>

// RNN1DGeneral: B=16384, L=64, H=64, DEPTH=2, D_L=2, D_C=8, LPF=0.5
// R14: single Wh1 pin + EXPLICIT top-of-loop staging of all 16 Wh0
// LDS.128 (latency drains under 32 register-operand MMAs), and the
// 2-class head reduced to ONE difference dot product:
//   z_sel - lse(z0,z1) = -softplus(+-(z1-z0)).

__device__ __forceinline__ void mmaf16(uint32_t& d0, uint32_t& d1,
    uint32_t a0, uint32_t a1, uint32_t a2, uint32_t a3,
    uint32_t b0, uint32_t b1)
{
    asm("mma.sync.aligned.m16n8k16.row.col.f16.f16.f16.f16 "
        "{%0,%1},{%2,%3,%4,%5},{%6,%7},{%0,%1};"
        : "+r"(d0), "+r"(d1)
        : "r"(a0), "r"(a1), "r"(a2), "r"(a3), "r"(b0), "r"(b1));
}

__device__ __forceinline__ void mmaf16_init(uint32_t& d0, uint32_t& d1,
    uint32_t a0, uint32_t a1, uint32_t a2, uint32_t a3,
    uint32_t b0, uint32_t b1, uint32_t c0, uint32_t c1)
{
    asm("mma.sync.aligned.m16n8k16.row.col.f16.f16.f16.f16 "
        "{%0,%1},{%2,%3,%4,%5},{%6,%7},{%8,%9};"
        : "=r"(d0), "=r"(d1)
        : "r"(a0), "r"(a1), "r"(a2), "r"(a3), "r"(b0), "r"(b1),
          "r"(c0), "r"(c1));
}

__device__ __forceinline__ uint32_t pack2(float lo, float hi) {
    __half2 h = __floats2half2_rn(lo, hi);
    return *reinterpret_cast<const uint32_t*>(&h);
}

__device__ __forceinline__ uint32_t elu_h2(uint32_t u) {
    const uint32_t LOG2E2 = 0x3DC53DC5u;
    const uint32_t ONE2   = 0x3C003C00u;
    uint32_t zero = 0u;
    uint32_t t, e, em1, mx, mn, r;
    asm("mul.rn.f16x2 %0, %1, %2;" : "=r"(t) : "r"(u), "r"(LOG2E2));
    asm("ex2.approx.f16x2 %0, %1;" : "=r"(e) : "r"(t));
    asm("sub.rn.f16x2 %0, %1, %2;" : "=r"(em1) : "r"(e), "r"(ONE2));
    asm("max.f16x2 %0, %1, %2;" : "=r"(mx) : "r"(u), "r"(zero));
    asm("min.f16x2 %0, %1, %2;" : "=r"(mn) : "r"(em1), "r"(zero));
    asm("add.rn.f16x2 %0, %1, %2;" : "=r"(r) : "r"(mx), "r"(mn));
    return r;
}

__device__ __forceinline__ void hfma2_acc(uint32_t& acc, uint32_t a, uint32_t b) {
    asm("fma.rn.f16x2 %0, %1, %2, %0;" : "+r"(acc) : "r"(a), "r"(b));
}

__global__ void __launch_bounds__(256, 1) rnn_fused(
    const int*   __restrict__ x,     // [16384, 65]
    const float* __restrict__ Win0,  // [2, 64]
    const float* __restrict__ Win1,  // [64, 64]
    const float* __restrict__ Wh,    // [2, 64, 64]
    const float* __restrict__ bvec,  // [2, 64]
    const float* __restrict__ Wlat,  // [64, 2]
    const float* __restrict__ blat,  // [2]
    const float* __restrict__ Wcav,  // [128, 8]
    const float* __restrict__ bcav,  // [8]
    float*       __restrict__ out)   // [16384]
{
    __shared__ uint4    sW4[3 * 4 * 4 * 32];  // l: 0=Wh0, 1=Win1, 2=Wh1 (24 KB)
    __shared__ uint32_t sVh[3 * 36];          // pack2(V[i][8nt+2m],+1) at i*36+4nt+m
    __shared__ uint32_t sB1h[32];             // pack2(b1[8g+2m],+1) at 4g+m
    __shared__ uint32_t sWd2[32];             // pack2(Wlat[col][1]-[col][0], ...) at 4g+m
    __shared__ float    sCav[128][8];
    __shared__ float    sB[10];               // [0..7]=bcav, [8]=blat1-blat0

    const int tid = threadIdx.x;

    for (int i = tid; i < 3 * 4 * 4 * 32; i += 256) {
        int lane_ = i & 31, ntp_ = (i >> 5) & 3, kt_ = (i >> 7) & 3, l_ = i >> 9;
        int q_ = lane_ >> 2, m_ = lane_ & 3;
        int k0 = 16 * kt_ + 2 * m_;
        int n0 = 16 * ntp_ + q_;
        int n1 = n0 + 8;
        const float* src = (l_ == 0) ? Wh : (l_ == 1 ? Win1 : (Wh + 4096));
        uint4 u;
        u.x = pack2(src[k0 * 64 + n0],       src[(k0 + 1) * 64 + n0]);
        u.y = pack2(src[(k0 + 8) * 64 + n0], src[(k0 + 9) * 64 + n0]);
        u.z = pack2(src[k0 * 64 + n1],       src[(k0 + 1) * 64 + n1]);
        u.w = pack2(src[(k0 + 8) * 64 + n1], src[(k0 + 9) * 64 + n1]);
        sW4[i] = u;
    }
    for (int i = tid; i < 128 * 8; i += 256)
        (reinterpret_cast<float*>(sCav))[i] = Wcav[i];
    if (tid < 96) {
        int i = tid >> 5, idx = tid & 31;
        int nt_ = idx >> 2, mm = idx & 3;
        int c = 8 * nt_ + 2 * mm;
        float lo, hi;
        if (i == 2) { lo = bvec[c]; hi = bvec[c + 1]; }
        else { lo = Win0[64 * i + c] + bvec[c]; hi = Win0[64 * i + c + 1] + bvec[c + 1]; }
        sVh[i * 36 + idx] = pack2(lo, hi);
    }
    if (tid < 32) {
        int g = tid >> 2, mm = tid & 3;
        int col = 8 * g + 2 * mm;
        sWd2[tid] = pack2(Wlat[2 * col + 1] - Wlat[2 * col],
                          Wlat[2 * col + 3] - Wlat[2 * col + 2]);
        sB1h[tid] = pack2(bvec[64 + col], bvec[64 + col + 1]);
    }
    if (tid < 8) sB[tid] = bcav[tid];
    if (tid == 0) sB[8] = blat[1] - blat[0];
    __syncthreads();

    const int lane = tid & 31, warp = tid >> 5;
    const int q = lane >> 2, m = lane & 3;
    const int rowbase = blockIdx.x * 128 + warp * 16;
    const uint4* wp4 = sW4 + lane;

    // ---- pin ONLY Wh1 (l=2): 16 uint4 = 64 regs ----
    uint4 wH1[16];
#pragma unroll
    for (int kt = 0; kt < 4; kt++)
#pragma unroll
        for (int ntp = 0; ntp < 4; ntp++)
            wH1[kt * 4 + ntp] = wp4[((2 * 4 + kt) * 4 + ntp) * 32];

    // pack per-row input bits; h in {0,1} -> row = rowbase + q + 8*h
    uint64_t xb[2];
    int xl[2];
#pragma unroll
    for (int rr = 0; rr < 2; rr++) {
        int r = rowbase + q + rr * 8;
        const int* xr = x + r * 65;
        uint64_t bits = 0;
#pragma unroll 8
        for (int t = 0; t < 64; t++)
            bits |= ((uint64_t)(xr[t] & 1)) << t;
        xb[rr] = bits;
        xl[rr] = xr[64] & 7;
    }

    const float bld = sB[8];

    // hidden state, packed post-ELU half2; h0(0)=elu(b0), h1(-1)=0
    uint32_t h0d[8][2], h1d[8][2];
#pragma unroll
    for (int nt = 0; nt < 8; nt++) {
        uint32_t v = elu_h2(sVh[2 * 36 + 4 * nt + m]);
        h0d[nt][0] = v; h0d[nt][1] = v;
        h1d[nt][0] = 0u; h1d[nt][1] = 0u;
    }

    float lp[2] = {0.f, 0.f};
    uint32_t d1s[8][2], d2s[8][2];

#pragma unroll 1
    for (int t = 0; t < 65; t++) {
        const bool last = (t == 64);

        // ---- stage Wh0 fragments FIRST: latency drains under layer1A ----
        uint4 wst[16];
        if (!last) {
#pragma unroll
            for (int kt = 0; kt < 4; kt++)
#pragma unroll
                for (int ntp = 0; ntp < 4; ntp++)
                    wst[kt * 4 + ntp] = wp4[((0 * 4 + kt) * 4 + ntp) * 32];
        }

        // layer1 A: d2s = b1 + h1(t-1)@Wh1  (register weights)
#pragma unroll
        for (int ntp = 0; ntp < 4; ntp++) {
            uint4 u = wH1[ntp];
            uint32_t c0 = sB1h[4 * (2 * ntp) + m];
            uint32_t c1 = sB1h[4 * (2 * ntp + 1) + m];
            mmaf16_init(d2s[2 * ntp][0], d2s[2 * ntp][1],
                h1d[0][0], h1d[0][1], h1d[1][0], h1d[1][1], u.x, u.y, c0, c0);
            mmaf16_init(d2s[2 * ntp + 1][0], d2s[2 * ntp + 1][1],
                h1d[0][0], h1d[0][1], h1d[1][0], h1d[1][1], u.z, u.w, c1, c1);
        }
#pragma unroll
        for (int kt = 1; kt < 4; kt++)
#pragma unroll
            for (int ntp = 0; ntp < 4; ntp++) {
                uint4 u = wH1[kt * 4 + ntp];
                mmaf16(d2s[2 * ntp][0], d2s[2 * ntp][1],
                    h1d[2 * kt][0], h1d[2 * kt][1],
                    h1d[2 * kt + 1][0], h1d[2 * kt + 1][1], u.x, u.y);
                mmaf16(d2s[2 * ntp + 1][0], d2s[2 * ntp + 1][1],
                    h1d[2 * kt][0], h1d[2 * kt][1],
                    h1d[2 * kt + 1][0], h1d[2 * kt + 1][1], u.z, u.w);
            }

        // layer0(next): d1s = V[x_t] + h0(t)@Wh0  (staged weights)
        if (!last) {
            int i0 = (int)((xb[0] >> t) & 1ull);
            int i1 = (int)((xb[1] >> t) & 1ull);
#pragma unroll
            for (int ntp = 0; ntp < 4; ntp++) {
                uint4 u = wst[ntp];
                int a0i = 2 * ntp, a1i = 2 * ntp + 1;
                uint32_t ca0 = sVh[i0 * 36 + 4 * a0i + m];
                uint32_t cb0 = sVh[i1 * 36 + 4 * a0i + m];
                uint32_t ca1 = sVh[i0 * 36 + 4 * a1i + m];
                uint32_t cb1 = sVh[i1 * 36 + 4 * a1i + m];
                mmaf16_init(d1s[a0i][0], d1s[a0i][1],
                    h0d[0][0], h0d[0][1], h0d[1][0], h0d[1][1], u.x, u.y, ca0, cb0);
                mmaf16_init(d1s[a1i][0], d1s[a1i][1],
                    h0d[0][0], h0d[0][1], h0d[1][0], h0d[1][1], u.z, u.w, ca1, cb1);
            }
#pragma unroll
            for (int kt = 1; kt < 4; kt++)
#pragma unroll
                for (int ntp = 0; ntp < 4; ntp++) {
                    uint4 u = wst[kt * 4 + ntp];
                    mmaf16(d1s[2 * ntp][0], d1s[2 * ntp][1],
                        h0d[2 * kt][0], h0d[2 * kt][1],
                        h0d[2 * kt + 1][0], h0d[2 * kt + 1][1], u.x, u.y);
                    mmaf16(d1s[2 * ntp + 1][0], d1s[2 * ntp + 1][1],
                        h0d[2 * kt][0], h0d[2 * kt][1],
                        h0d[2 * kt + 1][0], h0d[2 * kt + 1][1], u.z, u.w);
                }
        }

        // layer1 B: d2s += h0(t)@Win1  (inline SMEM loads; hidden by layer0 MMAs)
#pragma unroll
        for (int kt = 0; kt < 4; kt++)
#pragma unroll
            for (int ntp = 0; ntp < 4; ntp++) {
                uint4 u = wp4[((1 * 4 + kt) * 4 + ntp) * 32];
                mmaf16(d2s[2 * ntp][0], d2s[2 * ntp][1],
                    h0d[2 * kt][0], h0d[2 * kt][1],
                    h0d[2 * kt + 1][0], h0d[2 * kt + 1][1], u.x, u.y);
                mmaf16(d2s[2 * ntp + 1][0], d2s[2 * ntp + 1][1],
                    h0d[2 * kt][0], h0d[2 * kt][1],
                    h0d[2 * kt + 1][0], h0d[2 * kt + 1][1], u.z, u.w);
            }

        // head(t-1): single difference-logit dot; lp -= 0.5*softplus(+-d)
        if (t > 0) {
#pragma unroll
            for (int h = 0; h < 2; h++) {
                uint32_t za = 0u;
#pragma unroll
                for (int g = 0; g < 8; g++)
                    hfma2_acc(za, h1d[g][h], sWd2[4 * g + m]);
                float2 f = __half22float2(*reinterpret_cast<__half2*>(&za));
                float d = f.x + f.y;
                d += __shfl_xor_sync(0xffffffffu, d, 1);
                d += __shfl_xor_sync(0xffffffffu, d, 2);
                d += bld;                       // d = z1 - z0
                int bit = (int)((xb[h] >> (t - 1)) & 1ull);
                float delta = bit ? -d : d;     // z_other - z_selected
                float sp = fmaxf(delta, 0.f)
                         + __logf(1.f + __expf(-fabsf(delta)));
                lp[h] -= 0.5f * sp;
            }
        }

        // activations (in place on D)
#pragma unroll
        for (int nt = 0; nt < 8; nt++) {
            h1d[nt][0] = elu_h2(d2s[nt][0]);
            h1d[nt][1] = elu_h2(d2s[nt][1]);
        }
        if (!last) {
#pragma unroll
            for (int nt = 0; nt < 8; nt++) {
                h0d[nt][0] = elu_h2(d1s[nt][0]);
                h0d[nt][1] = elu_h2(d1s[nt][1]);
            }
        }
    }
    // h0d = h0(64), h1d = h1(64)

    // cavity head
#pragma unroll
    for (int h = 0; h < 2; h++) {
        float zc[8];
#pragma unroll
        for (int c = 0; c < 8; c++) zc[c] = 0.f;
#pragma unroll
        for (int nt = 0; nt < 8; nt++) {
            __half2 ha = *reinterpret_cast<const __half2*>(&h0d[nt][h]);
            __half2 hb = *reinterpret_cast<const __half2*>(&h1d[nt][h]);
            float v0 = __half2float(__low2half(ha));
            float v1 = __half2float(__high2half(ha));
            float w0 = __half2float(__low2half(hb));
            float w1 = __half2float(__high2half(hb));
            int col = 8 * nt + 2 * m;
#pragma unroll
            for (int c = 0; c < 8; c++) {
                zc[c] += v0 * sCav[col][c] + v1 * sCav[col + 1][c]
                       + w0 * sCav[64 + col][c] + w1 * sCav[64 + col + 1][c];
            }
        }
#pragma unroll
        for (int c = 0; c < 8; c++) {
            zc[c] += __shfl_xor_sync(0xffffffffu, zc[c], 1);
            zc[c] += __shfl_xor_sync(0xffffffffu, zc[c], 2);
            zc[c] += sB[c];
        }
        float mx = zc[0];
#pragma unroll
        for (int c = 1; c < 8; c++) mx = fmaxf(mx, zc[c]);
        float s = 0.f;
#pragma unroll
        for (int c = 0; c < 8; c++) s += __expf(zc[c] - mx);
        float lse = mx + __logf(s);
        float zsel = zc[0];
#pragma unroll
        for (int c = 1; c < 8; c++) if (xl[h] == c) zsel = zc[c];
        float total = lp[h] + 0.5f * (zsel - lse);
        if (m == 0)
            out[rowbase + q + 8 * h] = total;
    }
}

extern "C" void kernel_launch(void* const* d_in, const int* in_sizes, int n_in,
                              void* d_out, int out_size) {
    (void)in_sizes; (void)n_in; (void)out_size;
    const int*   x    = (const int*)d_in[0];
    const float* Win0 = (const float*)d_in[1];
    const float* Win1 = (const float*)d_in[2];
    const float* Wh   = (const float*)d_in[3];
    const float* b    = (const float*)d_in[4];
    const float* Wlat = (const float*)d_in[5];
    const float* blat = (const float*)d_in[6];
    const float* Wcav = (const float*)d_in[7];
    const float* bcav = (const float*)d_in[8];
    float* out = (float*)d_out;
    rnn_fused<<<128, 256>>>(x, Win0, Win1, Wh, b, Wlat, blat, Wcav, bcav, out);
}

// round 15
// speedup vs baseline: 1.0859x; 1.0859x over previous
#include <cuda_runtime.h>
#include <cuda_fp16.h>
#include <stdint.h>

// RNN1DGeneral: B=16384, L=64, H=64, DEPTH=2, D_L=2, D_C=8, LPF=0.5
// R15 = R13 (best: Wh1+Win1 pinned, Wh0 inline, tables in SMEM) with ONLY
// the head swapped for the difference-logit form:
//   z_sel - lse(z0,z1) = -softplus(+-(z1-z0))
// (half the head FMAs, half the SHFLs, one fewer MUFU per warp-step).

__device__ __forceinline__ void mmaf16(uint32_t& d0, uint32_t& d1,
    uint32_t a0, uint32_t a1, uint32_t a2, uint32_t a3,
    uint32_t b0, uint32_t b1)
{
    asm("mma.sync.aligned.m16n8k16.row.col.f16.f16.f16.f16 "
        "{%0,%1},{%2,%3,%4,%5},{%6,%7},{%0,%1};"
        : "+r"(d0), "+r"(d1)
        : "r"(a0), "r"(a1), "r"(a2), "r"(a3), "r"(b0), "r"(b1));
}

__device__ __forceinline__ void mmaf16_init(uint32_t& d0, uint32_t& d1,
    uint32_t a0, uint32_t a1, uint32_t a2, uint32_t a3,
    uint32_t b0, uint32_t b1, uint32_t c0, uint32_t c1)
{
    asm("mma.sync.aligned.m16n8k16.row.col.f16.f16.f16.f16 "
        "{%0,%1},{%2,%3,%4,%5},{%6,%7},{%8,%9};"
        : "=r"(d0), "=r"(d1)
        : "r"(a0), "r"(a1), "r"(a2), "r"(a3), "r"(b0), "r"(b1),
          "r"(c0), "r"(c1));
}

__device__ __forceinline__ uint32_t pack2(float lo, float hi) {
    __half2 h = __floats2half2_rn(lo, hi);
    return *reinterpret_cast<const uint32_t*>(&h);
}

__device__ __forceinline__ uint32_t elu_h2(uint32_t u) {
    const uint32_t LOG2E2 = 0x3DC53DC5u;
    const uint32_t ONE2   = 0x3C003C00u;
    uint32_t zero = 0u;
    uint32_t t, e, em1, mx, mn, r;
    asm("mul.rn.f16x2 %0, %1, %2;" : "=r"(t) : "r"(u), "r"(LOG2E2));
    asm("ex2.approx.f16x2 %0, %1;" : "=r"(e) : "r"(t));
    asm("sub.rn.f16x2 %0, %1, %2;" : "=r"(em1) : "r"(e), "r"(ONE2));
    asm("max.f16x2 %0, %1, %2;" : "=r"(mx) : "r"(u), "r"(zero));
    asm("min.f16x2 %0, %1, %2;" : "=r"(mn) : "r"(em1), "r"(zero));
    asm("add.rn.f16x2 %0, %1, %2;" : "=r"(r) : "r"(mx), "r"(mn));
    return r;
}

__device__ __forceinline__ void hfma2_acc(uint32_t& acc, uint32_t a, uint32_t b) {
    asm("fma.rn.f16x2 %0, %1, %2, %0;" : "+r"(acc) : "r"(a), "r"(b));
}

__global__ void __launch_bounds__(256, 1) rnn_fused(
    const int*   __restrict__ x,     // [16384, 65]
    const float* __restrict__ Win0,  // [2, 64]
    const float* __restrict__ Win1,  // [64, 64]
    const float* __restrict__ Wh,    // [2, 64, 64]
    const float* __restrict__ bvec,  // [2, 64]
    const float* __restrict__ Wlat,  // [64, 2]
    const float* __restrict__ blat,  // [2]
    const float* __restrict__ Wcav,  // [128, 8]
    const float* __restrict__ bcav,  // [8]
    float*       __restrict__ out)   // [16384]
{
    __shared__ uint4    sW4[3 * 4 * 4 * 32];  // l: 0=Wh0, 1=Win1, 2=Wh1 (24 KB)
    __shared__ uint32_t sVh[3 * 36];          // pack2(V[i][8nt+2m],+1) at i*36+4nt+m
    __shared__ uint32_t sB1h[32];             // pack2(b1[8g+2m],+1) at 4g+m
    __shared__ uint32_t sWd2[32];             // pack2(Wlat[col][1]-[col][0], ...) at 4g+m
    __shared__ float    sCav[128][8];
    __shared__ float    sB[10];               // [0..7]=bcav, [8]=blat1-blat0

    const int tid = threadIdx.x;

    for (int i = tid; i < 3 * 4 * 4 * 32; i += 256) {
        int lane_ = i & 31, ntp_ = (i >> 5) & 3, kt_ = (i >> 7) & 3, l_ = i >> 9;
        int q_ = lane_ >> 2, m_ = lane_ & 3;
        int k0 = 16 * kt_ + 2 * m_;
        int n0 = 16 * ntp_ + q_;
        int n1 = n0 + 8;
        const float* src = (l_ == 0) ? Wh : (l_ == 1 ? Win1 : (Wh + 4096));
        uint4 u;
        u.x = pack2(src[k0 * 64 + n0],       src[(k0 + 1) * 64 + n0]);
        u.y = pack2(src[(k0 + 8) * 64 + n0], src[(k0 + 9) * 64 + n0]);
        u.z = pack2(src[k0 * 64 + n1],       src[(k0 + 1) * 64 + n1]);
        u.w = pack2(src[(k0 + 8) * 64 + n1], src[(k0 + 9) * 64 + n1]);
        sW4[i] = u;
    }
    for (int i = tid; i < 128 * 8; i += 256)
        (reinterpret_cast<float*>(sCav))[i] = Wcav[i];
    if (tid < 96) {
        int i = tid >> 5, idx = tid & 31;
        int nt_ = idx >> 2, mm = idx & 3;
        int c = 8 * nt_ + 2 * mm;
        float lo, hi;
        if (i == 2) { lo = bvec[c]; hi = bvec[c + 1]; }
        else { lo = Win0[64 * i + c] + bvec[c]; hi = Win0[64 * i + c + 1] + bvec[c + 1]; }
        sVh[i * 36 + idx] = pack2(lo, hi);
    }
    if (tid < 32) {
        int g = tid >> 2, mm = tid & 3;
        int col = 8 * g + 2 * mm;
        sWd2[tid] = pack2(Wlat[2 * col + 1] - Wlat[2 * col],
                          Wlat[2 * col + 3] - Wlat[2 * col + 2]);
        sB1h[tid] = pack2(bvec[64 + col], bvec[64 + col + 1]);
    }
    if (tid < 8) sB[tid] = bcav[tid];
    if (tid == 0) sB[8] = blat[1] - blat[0];
    __syncthreads();

    const int lane = tid & 31, warp = tid >> 5;
    const int q = lane >> 2, m = lane & 3;
    const int rowbase = blockIdx.x * 128 + warp * 16;
    const uint4* wp4 = sW4 + lane;

    // ---- pin Wh1 (l=2) and Win1 (l=1): 32 uint4 = 128 regs ----
    uint4 wH1[16], wIn1[16];
#pragma unroll
    for (int kt = 0; kt < 4; kt++)
#pragma unroll
        for (int ntp = 0; ntp < 4; ntp++) {
            wH1[kt * 4 + ntp]  = wp4[((2 * 4 + kt) * 4 + ntp) * 32];
            wIn1[kt * 4 + ntp] = wp4[((1 * 4 + kt) * 4 + ntp) * 32];
        }

    // pack per-row input bits; h in {0,1} -> row = rowbase + q + 8*h
    uint64_t xb[2];
    int xl[2];
#pragma unroll
    for (int rr = 0; rr < 2; rr++) {
        int r = rowbase + q + rr * 8;
        const int* xr = x + r * 65;
        uint64_t bits = 0;
#pragma unroll 8
        for (int t = 0; t < 64; t++)
            bits |= ((uint64_t)(xr[t] & 1)) << t;
        xb[rr] = bits;
        xl[rr] = xr[64] & 7;
    }

    const float bld = sB[8];

    // hidden state, packed post-ELU half2; h0(0)=elu(b0), h1(-1)=0
    uint32_t h0d[8][2], h1d[8][2];
#pragma unroll
    for (int nt = 0; nt < 8; nt++) {
        uint32_t v = elu_h2(sVh[2 * 36 + 4 * nt + m]);
        h0d[nt][0] = v; h0d[nt][1] = v;
        h1d[nt][0] = 0u; h1d[nt][1] = 0u;
    }

    float lp[2] = {0.f, 0.f};
    uint32_t d1s[8][2], d2s[8][2];

#pragma unroll 1
    for (int t = 0; t < 65; t++) {
        const bool last = (t == 64);

        // layer1 A: d2s = b1 + h1(t-1)@Wh1  (register weights)
#pragma unroll
        for (int ntp = 0; ntp < 4; ntp++) {
            uint4 u = wH1[ntp];
            uint32_t c0 = sB1h[4 * (2 * ntp) + m];
            uint32_t c1 = sB1h[4 * (2 * ntp + 1) + m];
            mmaf16_init(d2s[2 * ntp][0], d2s[2 * ntp][1],
                h1d[0][0], h1d[0][1], h1d[1][0], h1d[1][1], u.x, u.y, c0, c0);
            mmaf16_init(d2s[2 * ntp + 1][0], d2s[2 * ntp + 1][1],
                h1d[0][0], h1d[0][1], h1d[1][0], h1d[1][1], u.z, u.w, c1, c1);
        }
#pragma unroll
        for (int kt = 1; kt < 4; kt++)
#pragma unroll
            for (int ntp = 0; ntp < 4; ntp++) {
                uint4 u = wH1[kt * 4 + ntp];
                mmaf16(d2s[2 * ntp][0], d2s[2 * ntp][1],
                    h1d[2 * kt][0], h1d[2 * kt][1],
                    h1d[2 * kt + 1][0], h1d[2 * kt + 1][1], u.x, u.y);
                mmaf16(d2s[2 * ntp + 1][0], d2s[2 * ntp + 1][1],
                    h1d[2 * kt][0], h1d[2 * kt][1],
                    h1d[2 * kt + 1][0], h1d[2 * kt + 1][1], u.z, u.w);
            }

        // layer0(next): d1s = V[x_t] + h0(t)@Wh0  (inline LDS.128)
        if (!last) {
            int i0 = (int)((xb[0] >> t) & 1ull);
            int i1 = (int)((xb[1] >> t) & 1ull);
#pragma unroll
            for (int ntp = 0; ntp < 4; ntp++) {
                uint4 u = wp4[((0 * 4 + 0) * 4 + ntp) * 32];
                int a0i = 2 * ntp, a1i = 2 * ntp + 1;
                uint32_t ca0 = sVh[i0 * 36 + 4 * a0i + m];
                uint32_t cb0 = sVh[i1 * 36 + 4 * a0i + m];
                uint32_t ca1 = sVh[i0 * 36 + 4 * a1i + m];
                uint32_t cb1 = sVh[i1 * 36 + 4 * a1i + m];
                mmaf16_init(d1s[a0i][0], d1s[a0i][1],
                    h0d[0][0], h0d[0][1], h0d[1][0], h0d[1][1], u.x, u.y, ca0, cb0);
                mmaf16_init(d1s[a1i][0], d1s[a1i][1],
                    h0d[0][0], h0d[0][1], h0d[1][0], h0d[1][1], u.z, u.w, ca1, cb1);
            }
#pragma unroll
            for (int kt = 1; kt < 4; kt++)
#pragma unroll
                for (int ntp = 0; ntp < 4; ntp++) {
                    uint4 u = wp4[((0 * 4 + kt) * 4 + ntp) * 32];
                    mmaf16(d1s[2 * ntp][0], d1s[2 * ntp][1],
                        h0d[2 * kt][0], h0d[2 * kt][1],
                        h0d[2 * kt + 1][0], h0d[2 * kt + 1][1], u.x, u.y);
                    mmaf16(d1s[2 * ntp + 1][0], d1s[2 * ntp + 1][1],
                        h0d[2 * kt][0], h0d[2 * kt][1],
                        h0d[2 * kt + 1][0], h0d[2 * kt + 1][1], u.z, u.w);
                }
        }

        // layer1 B: d2s += h0(t)@Win1  (register weights)
#pragma unroll
        for (int kt = 0; kt < 4; kt++)
#pragma unroll
            for (int ntp = 0; ntp < 4; ntp++) {
                uint4 u = wIn1[kt * 4 + ntp];
                mmaf16(d2s[2 * ntp][0], d2s[2 * ntp][1],
                    h0d[2 * kt][0], h0d[2 * kt][1],
                    h0d[2 * kt + 1][0], h0d[2 * kt + 1][1], u.x, u.y);
                mmaf16(d2s[2 * ntp + 1][0], d2s[2 * ntp + 1][1],
                    h0d[2 * kt][0], h0d[2 * kt][1],
                    h0d[2 * kt + 1][0], h0d[2 * kt + 1][1], u.z, u.w);
            }

        // head(t-1): single difference-logit dot; lp -= 0.5*softplus(+-d)
        if (t > 0) {
#pragma unroll
            for (int h = 0; h < 2; h++) {
                uint32_t za = 0u;
#pragma unroll
                for (int g = 0; g < 8; g++)
                    hfma2_acc(za, h1d[g][h], sWd2[4 * g + m]);
                float2 f = __half22float2(*reinterpret_cast<__half2*>(&za));
                float d = f.x + f.y;
                d += __shfl_xor_sync(0xffffffffu, d, 1);
                d += __shfl_xor_sync(0xffffffffu, d, 2);
                d += bld;                       // d = z1 - z0
                int bit = (int)((xb[h] >> (t - 1)) & 1ull);
                float delta = bit ? -d : d;     // z_other - z_selected
                float sp = fmaxf(delta, 0.f)
                         + __logf(1.f + __expf(-fabsf(delta)));
                lp[h] -= 0.5f * sp;
            }
        }

        // activations (in place on D)
#pragma unroll
        for (int nt = 0; nt < 8; nt++) {
            h1d[nt][0] = elu_h2(d2s[nt][0]);
            h1d[nt][1] = elu_h2(d2s[nt][1]);
        }
        if (!last) {
#pragma unroll
            for (int nt = 0; nt < 8; nt++) {
                h0d[nt][0] = elu_h2(d1s[nt][0]);
                h0d[nt][1] = elu_h2(d1s[nt][1]);
            }
        }
    }
    // h0d = h0(64), h1d = h1(64)

    // cavity head
#pragma unroll
    for (int h = 0; h < 2; h++) {
        float zc[8];
#pragma unroll
        for (int c = 0; c < 8; c++) zc[c] = 0.f;
#pragma unroll
        for (int nt = 0; nt < 8; nt++) {
            __half2 ha = *reinterpret_cast<const __half2*>(&h0d[nt][h]);
            __half2 hb = *reinterpret_cast<const __half2*>(&h1d[nt][h]);
            float v0 = __half2float(__low2half(ha));
            float v1 = __half2float(__high2half(ha));
            float w0 = __half2float(__low2half(hb));
            float w1 = __half2float(__high2half(hb));
            int col = 8 * nt + 2 * m;
#pragma unroll
            for (int c = 0; c < 8; c++) {
                zc[c] += v0 * sCav[col][c] + v1 * sCav[col + 1][c]
                       + w0 * sCav[64 + col][c] + w1 * sCav[64 + col + 1][c];
            }
        }
#pragma unroll
        for (int c = 0; c < 8; c++) {
            zc[c] += __shfl_xor_sync(0xffffffffu, zc[c], 1);
            zc[c] += __shfl_xor_sync(0xffffffffu, zc[c], 2);
            zc[c] += sB[c];
        }
        float mx = zc[0];
#pragma unroll
        for (int c = 1; c < 8; c++) mx = fmaxf(mx, zc[c]);
        float s = 0.f;
#pragma unroll
        for (int c = 0; c < 8; c++) s += __expf(zc[c] - mx);
        float lse = mx + __logf(s);
        float zsel = zc[0];
#pragma unroll
        for (int c = 1; c < 8; c++) if (xl[h] == c) zsel = zc[c];
        float total = lp[h] + 0.5f * (zsel - lse);
        if (m == 0)
            out[rowbase + q + 8 * h] = total;
    }
}

extern "C" void kernel_launch(void* const* d_in, const int* in_sizes, int n_in,
                              void* d_out, int out_size) {
    (void)in_sizes; (void)n_in; (void)out_size;
    const int*   x    = (const int*)d_in[0];
    const float* Win0 = (const float*)d_in[1];
    const float* Win1 = (const float*)d_in[2];
    const float* Wh   = (const float*)d_in[3];
    const float* b    = (const float*)d_in[4];
    const float* Wlat = (const float*)d_in[5];
    const float* blat = (const float*)d_in[6];
    const float* Wcav = (const float*)d_in[7];
    const float* bcav = (const float*)d_in[8];
    float* out = (float*)d_out;
    rnn_fused<<<128, 256>>>(x, Win0, Win1, Wh, b, Wlat, blat, Wcav, bcav, out);
}

// round 16
// speedup vs baseline: 1.1964x; 1.1017x over previous
#include <cuda_runtime.h>
#include <cuda_fp16.h>
#include <stdint.h>

// RNN1DGeneral: B=16384, L=64, H=64, DEPTH=2, D_L=2, D_C=8, LPF=0.5
// R16 = R13 (Wh1+Win1 pinned, Wh0 inline, tables in SMEM) with the h0
// activation SOFTWARE-ROTATED across the loop back-edge: ELU(d1s of t-1)
// executes after layer1A's 32 register MMAs (tensor shadow) and right
// before its first consumer (layer0), instead of in the serial tail.

__device__ __forceinline__ void mmaf16(uint32_t& d0, uint32_t& d1,
    uint32_t a0, uint32_t a1, uint32_t a2, uint32_t a3,
    uint32_t b0, uint32_t b1)
{
    asm("mma.sync.aligned.m16n8k16.row.col.f16.f16.f16.f16 "
        "{%0,%1},{%2,%3,%4,%5},{%6,%7},{%0,%1};"
        : "+r"(d0), "+r"(d1)
        : "r"(a0), "r"(a1), "r"(a2), "r"(a3), "r"(b0), "r"(b1));
}

__device__ __forceinline__ void mmaf16_init(uint32_t& d0, uint32_t& d1,
    uint32_t a0, uint32_t a1, uint32_t a2, uint32_t a3,
    uint32_t b0, uint32_t b1, uint32_t c0, uint32_t c1)
{
    asm("mma.sync.aligned.m16n8k16.row.col.f16.f16.f16.f16 "
        "{%0,%1},{%2,%3,%4,%5},{%6,%7},{%8,%9};"
        : "=r"(d0), "=r"(d1)
        : "r"(a0), "r"(a1), "r"(a2), "r"(a3), "r"(b0), "r"(b1),
          "r"(c0), "r"(c1));
}

__device__ __forceinline__ uint32_t pack2(float lo, float hi) {
    __half2 h = __floats2half2_rn(lo, hi);
    return *reinterpret_cast<const uint32_t*>(&h);
}

__device__ __forceinline__ uint32_t elu_h2(uint32_t u) {
    const uint32_t LOG2E2 = 0x3DC53DC5u;
    const uint32_t ONE2   = 0x3C003C00u;
    uint32_t zero = 0u;
    uint32_t t, e, em1, mx, mn, r;
    asm("mul.rn.f16x2 %0, %1, %2;" : "=r"(t) : "r"(u), "r"(LOG2E2));
    asm("ex2.approx.f16x2 %0, %1;" : "=r"(e) : "r"(t));
    asm("sub.rn.f16x2 %0, %1, %2;" : "=r"(em1) : "r"(e), "r"(ONE2));
    asm("max.f16x2 %0, %1, %2;" : "=r"(mx) : "r"(u), "r"(zero));
    asm("min.f16x2 %0, %1, %2;" : "=r"(mn) : "r"(em1), "r"(zero));
    asm("add.rn.f16x2 %0, %1, %2;" : "=r"(r) : "r"(mx), "r"(mn));
    return r;
}

__device__ __forceinline__ void hfma2_acc(uint32_t& acc, uint32_t a, uint32_t b) {
    asm("fma.rn.f16x2 %0, %1, %2, %0;" : "+r"(acc) : "r"(a), "r"(b));
}

__global__ void __launch_bounds__(256, 1) rnn_fused(
    const int*   __restrict__ x,     // [16384, 65]
    const float* __restrict__ Win0,  // [2, 64]
    const float* __restrict__ Win1,  // [64, 64]
    const float* __restrict__ Wh,    // [2, 64, 64]
    const float* __restrict__ bvec,  // [2, 64]
    const float* __restrict__ Wlat,  // [64, 2]
    const float* __restrict__ blat,  // [2]
    const float* __restrict__ Wcav,  // [128, 8]
    const float* __restrict__ bcav,  // [8]
    float*       __restrict__ out)   // [16384]
{
    __shared__ uint4    sW4[3 * 4 * 4 * 32];  // l: 0=Wh0, 1=Win1, 2=Wh1 (24 KB)
    __shared__ uint32_t sVh[3 * 36];          // pack2(V[i][8nt+2m],+1) at i*36+4nt+m
    __shared__ uint32_t sB1h[32];             // pack2(b1[8g+2m],+1) at 4g+m
    __shared__ uint2    sWl2[32];             // Wlat pairs at 4g+m
    __shared__ float    sCav[128][8];
    __shared__ float    sB[10];               // [0..7]=bcav, [8..9]=blat

    const int tid = threadIdx.x;

    for (int i = tid; i < 3 * 4 * 4 * 32; i += 256) {
        int lane_ = i & 31, ntp_ = (i >> 5) & 3, kt_ = (i >> 7) & 3, l_ = i >> 9;
        int q_ = lane_ >> 2, m_ = lane_ & 3;
        int k0 = 16 * kt_ + 2 * m_;
        int n0 = 16 * ntp_ + q_;
        int n1 = n0 + 8;
        const float* src = (l_ == 0) ? Wh : (l_ == 1 ? Win1 : (Wh + 4096));
        uint4 u;
        u.x = pack2(src[k0 * 64 + n0],       src[(k0 + 1) * 64 + n0]);
        u.y = pack2(src[(k0 + 8) * 64 + n0], src[(k0 + 9) * 64 + n0]);
        u.z = pack2(src[k0 * 64 + n1],       src[(k0 + 1) * 64 + n1]);
        u.w = pack2(src[(k0 + 8) * 64 + n1], src[(k0 + 9) * 64 + n1]);
        sW4[i] = u;
    }
    for (int i = tid; i < 128 * 8; i += 256)
        (reinterpret_cast<float*>(sCav))[i] = Wcav[i];
    if (tid < 96) {
        int i = tid >> 5, idx = tid & 31;
        int nt_ = idx >> 2, mm = idx & 3;
        int c = 8 * nt_ + 2 * mm;
        float lo, hi;
        if (i == 2) { lo = bvec[c]; hi = bvec[c + 1]; }
        else { lo = Win0[64 * i + c] + bvec[c]; hi = Win0[64 * i + c + 1] + bvec[c + 1]; }
        sVh[i * 36 + idx] = pack2(lo, hi);
    }
    if (tid < 32) {
        int g = tid >> 2, mm = tid & 3;
        int col = 8 * g + 2 * mm;
        uint2 w;
        w.x = pack2(Wlat[2 * col],     Wlat[2 * col + 2]);
        w.y = pack2(Wlat[2 * col + 1], Wlat[2 * col + 3]);
        sWl2[tid] = w;
        sB1h[tid] = pack2(bvec[64 + col], bvec[64 + col + 1]);
    }
    if (tid < 8) sB[tid] = bcav[tid];
    if (tid < 2) sB[8 + tid] = blat[tid];
    __syncthreads();

    const int lane = tid & 31, warp = tid >> 5;
    const int q = lane >> 2, m = lane & 3;
    const int rowbase = blockIdx.x * 128 + warp * 16;
    const uint4* wp4 = sW4 + lane;

    // ---- pin Wh1 (l=2) and Win1 (l=1): 32 uint4 = 128 regs ----
    uint4 wH1[16], wIn1[16];
#pragma unroll
    for (int kt = 0; kt < 4; kt++)
#pragma unroll
        for (int ntp = 0; ntp < 4; ntp++) {
            wH1[kt * 4 + ntp]  = wp4[((2 * 4 + kt) * 4 + ntp) * 32];
            wIn1[kt * 4 + ntp] = wp4[((1 * 4 + kt) * 4 + ntp) * 32];
        }

    // pack per-row input bits; h in {0,1} -> row = rowbase + q + 8*h
    uint64_t xb[2];
    int xl[2];
#pragma unroll
    for (int rr = 0; rr < 2; rr++) {
        int r = rowbase + q + rr * 8;
        const int* xr = x + r * 65;
        uint64_t bits = 0;
#pragma unroll 8
        for (int t = 0; t < 64; t++)
            bits |= ((uint64_t)(xr[t] & 1)) << t;
        xb[rr] = bits;
        xl[rr] = xr[64] & 7;
    }

    const float bl0 = sB[8], bl1 = sB[9];

    // hidden state, packed post-ELU half2; h0(0)=elu(b0), h1(-1)=0
    uint32_t h0d[8][2], h1d[8][2];
#pragma unroll
    for (int nt = 0; nt < 8; nt++) {
        uint32_t v = elu_h2(sVh[2 * 36 + 4 * nt + m]);
        h0d[nt][0] = v; h0d[nt][1] = v;
        h1d[nt][0] = 0u; h1d[nt][1] = 0u;
    }

    float lp[2] = {0.f, 0.f};
    uint32_t d1s[8][2], d2s[8][2];

#pragma unroll 1
    for (int t = 0; t < 65; t++) {
        const bool last = (t == 64);

        // layer1 A: d2s = b1 + h1(t-1)@Wh1  (register weights)
#pragma unroll
        for (int ntp = 0; ntp < 4; ntp++) {
            uint4 u = wH1[ntp];
            uint32_t c0 = sB1h[4 * (2 * ntp) + m];
            uint32_t c1 = sB1h[4 * (2 * ntp + 1) + m];
            mmaf16_init(d2s[2 * ntp][0], d2s[2 * ntp][1],
                h1d[0][0], h1d[0][1], h1d[1][0], h1d[1][1], u.x, u.y, c0, c0);
            mmaf16_init(d2s[2 * ntp + 1][0], d2s[2 * ntp + 1][1],
                h1d[0][0], h1d[0][1], h1d[1][0], h1d[1][1], u.z, u.w, c1, c1);
        }
#pragma unroll
        for (int kt = 1; kt < 4; kt++)
#pragma unroll
            for (int ntp = 0; ntp < 4; ntp++) {
                uint4 u = wH1[kt * 4 + ntp];
                mmaf16(d2s[2 * ntp][0], d2s[2 * ntp][1],
                    h1d[2 * kt][0], h1d[2 * kt][1],
                    h1d[2 * kt + 1][0], h1d[2 * kt + 1][1], u.x, u.y);
                mmaf16(d2s[2 * ntp + 1][0], d2s[2 * ntp + 1][1],
                    h1d[2 * kt][0], h1d[2 * kt][1],
                    h1d[2 * kt + 1][0], h1d[2 * kt + 1][1], u.z, u.w);
            }

        // ROTATED: ELU(d1s from t-1) -> h0d = h0(t), issued in the tensor
        // shadow of layer1A; first consumer is layer0 below.
        if (t > 0) {
#pragma unroll
            for (int nt = 0; nt < 8; nt++) {
                h0d[nt][0] = elu_h2(d1s[nt][0]);
                h0d[nt][1] = elu_h2(d1s[nt][1]);
            }
        }

        // layer0(next): d1s = V[x_t] + h0(t)@Wh0  (inline LDS.128)
        if (!last) {
            int i0 = (int)((xb[0] >> t) & 1ull);
            int i1 = (int)((xb[1] >> t) & 1ull);
#pragma unroll
            for (int ntp = 0; ntp < 4; ntp++) {
                uint4 u = wp4[((0 * 4 + 0) * 4 + ntp) * 32];
                int a0i = 2 * ntp, a1i = 2 * ntp + 1;
                uint32_t ca0 = sVh[i0 * 36 + 4 * a0i + m];
                uint32_t cb0 = sVh[i1 * 36 + 4 * a0i + m];
                uint32_t ca1 = sVh[i0 * 36 + 4 * a1i + m];
                uint32_t cb1 = sVh[i1 * 36 + 4 * a1i + m];
                mmaf16_init(d1s[a0i][0], d1s[a0i][1],
                    h0d[0][0], h0d[0][1], h0d[1][0], h0d[1][1], u.x, u.y, ca0, cb0);
                mmaf16_init(d1s[a1i][0], d1s[a1i][1],
                    h0d[0][0], h0d[0][1], h0d[1][0], h0d[1][1], u.z, u.w, ca1, cb1);
            }
#pragma unroll
            for (int kt = 1; kt < 4; kt++)
#pragma unroll
                for (int ntp = 0; ntp < 4; ntp++) {
                    uint4 u = wp4[((0 * 4 + kt) * 4 + ntp) * 32];
                    mmaf16(d1s[2 * ntp][0], d1s[2 * ntp][1],
                        h0d[2 * kt][0], h0d[2 * kt][1],
                        h0d[2 * kt + 1][0], h0d[2 * kt + 1][1], u.x, u.y);
                    mmaf16(d1s[2 * ntp + 1][0], d1s[2 * ntp + 1][1],
                        h0d[2 * kt][0], h0d[2 * kt][1],
                        h0d[2 * kt + 1][0], h0d[2 * kt + 1][1], u.z, u.w);
                }
        }

        // layer1 B: d2s += h0(t)@Win1  (register weights)
#pragma unroll
        for (int kt = 0; kt < 4; kt++)
#pragma unroll
            for (int ntp = 0; ntp < 4; ntp++) {
                uint4 u = wIn1[kt * 4 + ntp];
                mmaf16(d2s[2 * ntp][0], d2s[2 * ntp][1],
                    h0d[2 * kt][0], h0d[2 * kt][1],
                    h0d[2 * kt + 1][0], h0d[2 * kt + 1][1], u.x, u.y);
                mmaf16(d2s[2 * ntp + 1][0], d2s[2 * ntp + 1][1],
                    h0d[2 * kt][0], h0d[2 * kt][1],
                    h0d[2 * kt + 1][0], h0d[2 * kt + 1][1], u.z, u.w);
            }

        // head(t-1) from h1d = h1(t-1), in the MMA shadow
        if (t > 0) {
#pragma unroll
            for (int h = 0; h < 2; h++) {
                uint32_t za0 = 0u, za1 = 0u;
#pragma unroll
                for (int g = 0; g < 8; g++) {
                    uint32_t u = h1d[g][h];
                    uint2 w = sWl2[4 * g + m];
                    hfma2_acc(za0, u, w.x);
                    hfma2_acc(za1, u, w.y);
                }
                float2 f0 = __half22float2(*reinterpret_cast<__half2*>(&za0));
                float2 f1 = __half22float2(*reinterpret_cast<__half2*>(&za1));
                float z0 = f0.x + f0.y, z1 = f1.x + f1.y;
                z0 += __shfl_xor_sync(0xffffffffu, z0, 1);
                z0 += __shfl_xor_sync(0xffffffffu, z0, 2);
                z1 += __shfl_xor_sync(0xffffffffu, z1, 1);
                z1 += __shfl_xor_sync(0xffffffffu, z1, 2);
                z0 += bl0; z1 += bl1;
                int bit = (int)((xb[h] >> (t - 1)) & 1ull);
                float mx = fmaxf(z0, z1);
                float lse = mx + __logf(1.f + __expf(-fabsf(z0 - z1)));
                float zsel = bit ? z1 : z0;
                lp[h] += 0.5f * (zsel - lse);
            }
        }

        // tail: only the h1 activation remains serial
#pragma unroll
        for (int nt = 0; nt < 8; nt++) {
            h1d[nt][0] = elu_h2(d2s[nt][0]);
            h1d[nt][1] = elu_h2(d2s[nt][1]);
        }
    }
    // h0d = h0(64), h1d = h1(64)

    // cavity head
#pragma unroll
    for (int h = 0; h < 2; h++) {
        float zc[8];
#pragma unroll
        for (int c = 0; c < 8; c++) zc[c] = 0.f;
#pragma unroll
        for (int nt = 0; nt < 8; nt++) {
            __half2 ha = *reinterpret_cast<const __half2*>(&h0d[nt][h]);
            __half2 hb = *reinterpret_cast<const __half2*>(&h1d[nt][h]);
            float v0 = __half2float(__low2half(ha));
            float v1 = __half2float(__high2half(ha));
            float w0 = __half2float(__low2half(hb));
            float w1 = __half2float(__high2half(hb));
            int col = 8 * nt + 2 * m;
#pragma unroll
            for (int c = 0; c < 8; c++) {
                zc[c] += v0 * sCav[col][c] + v1 * sCav[col + 1][c]
                       + w0 * sCav[64 + col][c] + w1 * sCav[64 + col + 1][c];
            }
        }
#pragma unroll
        for (int c = 0; c < 8; c++) {
            zc[c] += __shfl_xor_sync(0xffffffffu, zc[c], 1);
            zc[c] += __shfl_xor_sync(0xffffffffu, zc[c], 2);
            zc[c] += sB[c];
        }
        float mx = zc[0];
#pragma unroll
        for (int c = 1; c < 8; c++) mx = fmaxf(mx, zc[c]);
        float s = 0.f;
#pragma unroll
        for (int c = 0; c < 8; c++) s += __expf(zc[c] - mx);
        float lse = mx + __logf(s);
        float zsel = zc[0];
#pragma unroll
        for (int c = 1; c < 8; c++) if (xl[h] == c) zsel = zc[c];
        float total = lp[h] + 0.5f * (zsel - lse);
        if (m == 0)
            out[rowbase + q + 8 * h] = total;
    }
}

extern "C" void kernel_launch(void* const* d_in, const int* in_sizes, int n_in,
                              void* d_out, int out_size) {
    (void)in_sizes; (void)n_in; (void)out_size;
    const int*   x    = (const int*)d_in[0];
    const float* Win0 = (const float*)d_in[1];
    const float* Win1 = (const float*)d_in[2];
    const float* Wh   = (const float*)d_in[3];
    const float* b    = (const float*)d_in[4];
    const float* Wlat = (const float*)d_in[5];
    const float* blat = (const float*)d_in[6];
    const float* Wcav = (const float*)d_in[7];
    const float* bcav = (const float*)d_in[8];
    float* out = (float*)d_out;
    rnn_fused<<<128, 256>>>(x, Win0, Win1, Wh, b, Wlat, blat, Wcav, bcav, out);
}